// round 3
// baseline (speedup 1.0000x reference)
#include <cuda_runtime.h>
#include <cuda_bf16.h>
#include <cstdint>

// ============================================================
// Problem constants
// ============================================================
#define BB    32
#define HID   128
#define ATTN  128
#define S_TOTAL   8192               // T*N positions per batch
#define TILE_S    128
#define TILES_PB  (S_TOTAL / TILE_S) // 64
#define CPB       8                  // CTAs per batch
#define TILES_PER_CTA (TILES_PB / CPB) // 8
#define NCTA      (BB * CPB)         // 256

// SMEM tile: bf16 [128 rows][128 cols] with 8-half (16B) row pad
#define PITCH_H   136                // halves per row
#define PITCH_B   (PITCH_H * 2)      // 272 bytes
#define TILE_BYTES (128 * PITCH_B)   // 34816

// SMEM layout (bytes)
#define SMEM_RED    0                 // float[8]
#define SMEM_SCORE  32                // float[128]
#define SMEM_SW     576               // float[128] softmax weights
#define SMEM_BIASV  1152              // float2[128]
#define SMEM_A      2176              // history tile
#define SMEM_W      (2176 + TILE_BYTES)      // 36992
#define SMEM_TOTAL  (36992 + TILE_BYTES)     // 71808

// ============================================================
// Partial-result scratch (static device memory: allowed)
// ============================================================
__device__ float g_pm[NCTA];
__device__ float g_pl[NCTA];
__device__ float g_pacc[NCTA * HID];

// ============================================================
// Helpers
// ============================================================
__device__ __forceinline__ uint32_t smem_to_u32(const void* p) {
    uint32_t a;
    asm("{ .reg .u64 t; cvta.to.shared.u64 t, %1; cvt.u32.u64 %0, t; }" : "=r"(a) : "l"(p));
    return a;
}

#define LDSM_X4(r, addr) \
    asm volatile("ldmatrix.sync.aligned.m8n8.x4.shared.b16 {%0,%1,%2,%3}, [%4];" \
        : "=r"((r)[0]), "=r"((r)[1]), "=r"((r)[2]), "=r"((r)[3]) : "r"(addr))

__device__ __forceinline__ void mma16816(float* c, const uint32_t* a, uint32_t b0, uint32_t b1) {
    asm volatile(
        "mma.sync.aligned.m16n8k16.row.col.f32.bf16.bf16.f32 "
        "{%0,%1,%2,%3}, {%4,%5,%6,%7}, {%8,%9}, {%0,%1,%2,%3};"
        : "+f"(c[0]), "+f"(c[1]), "+f"(c[2]), "+f"(c[3])
        : "r"(a[0]), "r"(a[1]), "r"(a[2]), "r"(a[3]), "r"(b0), "r"(b1));
}

// Load a [128 x 128] fp32 row-major tile from gmem -> bf16 padded smem tile.
// Each warp owns one row per iteration (coalesced 512B LDG per warp).
__device__ __forceinline__ void load_tile_bf16(const float4* __restrict__ src4,
                                               char* dst, int wid, int lane) {
#pragma unroll 8
    for (int it = 0; it < 32; ++it) {
        int r = it * 4 + wid;
        float4 v = __ldg(&src4[r * 32 + lane]);
        uint32_t p0, p1;
        asm("cvt.rn.bf16x2.f32 %0, %1, %2;" : "=r"(p0) : "f"(v.y), "f"(v.x));
        asm("cvt.rn.bf16x2.f32 %0, %1, %2;" : "=r"(p1) : "f"(v.w), "f"(v.z));
        *reinterpret_cast<uint2*>(dst + r * PITCH_B + lane * 8) = make_uint2(p0, p1);
    }
}

// ============================================================
// Main fused kernel
// ============================================================
__global__ void __launch_bounds__(128, 3) attn_main_kernel(
    const float* __restrict__ hist, const float* __restrict__ cur,
    const float* __restrict__ Wx,   const float* __restrict__ Wxb,
    const float* __restrict__ Wh,   const float* __restrict__ Whb,
    const float* __restrict__ vw)
{
    extern __shared__ __align__(16) char smem[];
    const int tid = threadIdx.x, wid = tid >> 5, lane = tid & 31;
    const int cta = blockIdx.x, b = cta >> 3, c = cta & 7;
    const uint32_t sbase = smem_to_u32(smem);

    // Wh -> bf16 padded smem (rows = attn dim a, cols = hid k). This is the
    // col-major KxN operand for mma row.col (k contiguous per a-row).
    load_tile_bf16(reinterpret_cast<const float4*>(Wh), smem + SMEM_W, wid, lane);

    // bias[a] = Whb[a] + Wxb[a] + Wx[a,:] . cur[b,:]
    {
        const float* wxa = Wx + tid * HID;
        const float* cb  = cur + b * HID;
        float s = Wxb[tid] + Whb[tid];
#pragma unroll 8
        for (int k = 0; k < HID; ++k) s = fmaf(__ldg(&wxa[k]), __ldg(&cb[k]), s);
        reinterpret_cast<float2*>(smem + SMEM_BIASV)[tid] = make_float2(s, __ldg(&vw[tid]));
    }
    __syncthreads();

    const float2* biasv = reinterpret_cast<const float2*>(smem + SMEM_BIASV);
    float* s_red   = reinterpret_cast<float*>(smem + SMEM_RED);
    float* s_score = reinterpret_cast<float*>(smem + SMEM_SCORE);
    float* s_w     = reinterpret_cast<float*>(smem + SMEM_SW);

    const uint32_t sA = sbase + SMEM_A;
    const uint32_t sW = sbase + SMEM_W;

    // Per-thread ldmatrix address offsets (bytes).
    const int g8 = lane & 7;
    const uint32_t rowA_off = (uint32_t)((((lane >> 3) & 1) * 8 + g8) * PITCH_B + (lane >> 4) * 16);
    const uint32_t rowB_off = (uint32_t)(((lane >> 4) * 8 + g8) * PITCH_B + ((lane >> 3) & 1) * 16);

    float m_run = __int_as_float(0xff800000);  // -inf
    float l_run = 0.f;
    float facc  = 0.f;                         // thread owns hid dim = tid

    for (int i = 0; i < TILES_PER_CTA; ++i) {
        const int tile = c + i * CPB;
        const float4* src4 = reinterpret_cast<const float4*>(
            hist + (size_t)(b * S_TOTAL + tile * TILE_S) * HID);
        load_tile_bf16(src4, smem + SMEM_A, wid, lane);
        __syncthreads();

        // ---- warp GEMM: proj = hist_tile @ Wh^T, fused tanh+v reduce ----
        float sp[2][2] = {{0.f, 0.f}, {0.f, 0.f}};   // [mtile][row-half]
#pragma unroll
        for (int nc = 0; nc < 4; ++nc) {             // 32 attn-cols per chunk
            float acc[2][4][4];
#pragma unroll
            for (int mt = 0; mt < 2; ++mt)
#pragma unroll
                for (int nt = 0; nt < 4; ++nt)
#pragma unroll
                    for (int r = 0; r < 4; ++r) acc[mt][nt][r] = 0.f;

#pragma unroll
            for (int k = 0; k < 8; ++k) {
                uint32_t afr[2][4], bfr[2][4];
#pragma unroll
                for (int mt = 0; mt < 2; ++mt)
                    LDSM_X4(afr[mt], sA + (uint32_t)((wid * 32 + mt * 16) * PITCH_B + k * 32) + rowA_off);
#pragma unroll
                for (int ntp = 0; ntp < 2; ++ntp)
                    LDSM_X4(bfr[ntp], sW + (uint32_t)((nc * 32 + ntp * 16) * PITCH_B + k * 32) + rowB_off);
#pragma unroll
                for (int mt = 0; mt < 2; ++mt)
#pragma unroll
                    for (int nt = 0; nt < 4; ++nt)
                        mma16816(acc[mt][nt], afr[mt],
                                 bfr[nt >> 1][(nt & 1) * 2], bfr[nt >> 1][(nt & 1) * 2 + 1]);
            }
            // chunk epilogue: tanh(proj + bias) * v, reduce over cols
#pragma unroll
            for (int mt = 0; mt < 2; ++mt)
#pragma unroll
                for (int nt = 0; nt < 4; ++nt) {
                    const int colb = nc * 32 + nt * 8 + 2 * (lane & 3);
                    const float2 bv0 = biasv[colb];
                    const float2 bv1 = biasv[colb + 1];
#pragma unroll
                    for (int rr = 0; rr < 2; ++rr) {
                        float x0 = acc[mt][nt][rr * 2 + 0] + bv0.x;
                        float x1 = acc[mt][nt][rr * 2 + 1] + bv1.x;
                        float t0, t1;
                        asm("tanh.approx.f32 %0, %1;" : "=f"(t0) : "f"(x0));
                        asm("tanh.approx.f32 %0, %1;" : "=f"(t1) : "f"(x1));
                        sp[mt][rr] = fmaf(t0, bv0.y, sp[mt][rr]);
                        sp[mt][rr] = fmaf(t1, bv1.y, sp[mt][rr]);
                    }
                }
        }
        // quad reduce -> scores to smem
#pragma unroll
        for (int mt = 0; mt < 2; ++mt)
#pragma unroll
            for (int rr = 0; rr < 2; ++rr) {
                float v = sp[mt][rr];
                v += __shfl_xor_sync(0xffffffffu, v, 1);
                v += __shfl_xor_sync(0xffffffffu, v, 2);
                if ((lane & 3) == 0)
                    s_score[wid * 32 + mt * 16 + rr * 8 + (lane >> 2)] = v;
            }
        __syncthreads();

        const float score = s_score[tid];

        // ---- block max ----
        float mt_ = score;
#pragma unroll
        for (int o = 16; o; o >>= 1) mt_ = fmaxf(mt_, __shfl_xor_sync(0xffffffffu, mt_, o));
        if (lane == 0) s_red[wid] = mt_;
        __syncthreads();
        const float tmax  = fmaxf(fmaxf(s_red[0], s_red[1]), fmaxf(s_red[2], s_red[3]));
        const float new_m = fmaxf(m_run, tmax);
        const float corr  = __expf(m_run - new_m);
        const float p     = __expf(score - new_m);

        // ---- block sum ----
        float ps = p;
#pragma unroll
        for (int o = 16; o; o >>= 1) ps += __shfl_xor_sync(0xffffffffu, ps, o);
        if (lane == 0) s_red[4 + wid] = ps;
        s_w[tid] = p;
        __syncthreads();

        l_run = l_run * corr + (s_red[4] + s_red[5] + s_red[6] + s_red[7]);
        m_run = new_m;

        // ---- weighted accumulate: thread = hid dim (column tid of A tile) ----
        facc *= corr;
        {
            const char* hb = smem + SMEM_A + tid * 2;
#pragma unroll 16
            for (int s2 = 0; s2 < TILE_S; ++s2) {
                uint16_t raw = *reinterpret_cast<const uint16_t*>(hb + s2 * PITCH_B);
                float hv = __uint_as_float(((uint32_t)raw) << 16);
                facc = fmaf(s_w[s2], hv, facc);
            }
        }
        __syncthreads();  // protect A tile + s_w before next iteration
    }

    if (tid == 0) { g_pm[cta] = m_run; g_pl[cta] = l_run; }
    g_pacc[cta * HID + tid] = facc;
}

// ============================================================
// Combine: merge 8 partials per batch, add cur_h
// ============================================================
__global__ void attn_combine_kernel(const float* __restrict__ cur, float* __restrict__ out)
{
    const int b = blockIdx.x, h = threadIdx.x;
    float M = __int_as_float(0xff800000);
#pragma unroll
    for (int j = 0; j < CPB; ++j) M = fmaxf(M, g_pm[b * CPB + j]);
    float L = 0.f, num = 0.f;
#pragma unroll
    for (int j = 0; j < CPB; ++j) {
        const int idx = b * CPB + j;
        const float e = expf(g_pm[idx] - M);
        L   += g_pl[idx] * e;
        num += g_pacc[idx * HID + h] * e;
    }
    out[b * HID + h] = cur[b * HID + h] + num / L;
}

// ============================================================
// Launch
// ============================================================
extern "C" void kernel_launch(void* const* d_in, const int* in_sizes, int n_in,
                              void* d_out, int out_size)
{
    (void)in_sizes; (void)n_in; (void)out_size;
    const float* cur  = (const float*)d_in[0];
    const float* hist = (const float*)d_in[1];
    const float* Wx   = (const float*)d_in[2];
    const float* Wxb  = (const float*)d_in[3];
    const float* Wh   = (const float*)d_in[4];
    const float* Whb  = (const float*)d_in[5];
    const float* vw   = (const float*)d_in[6];
    float* out = (float*)d_out;

    cudaFuncSetAttribute(attn_main_kernel,
                         cudaFuncAttributeMaxDynamicSharedMemorySize, SMEM_TOTAL);

    attn_main_kernel<<<NCTA, 128, SMEM_TOTAL>>>(hist, cur, Wx, Wxb, Wh, Whb, vw);
    attn_combine_kernel<<<BB, 128>>>(cur, out);
}

// round 4
// speedup vs baseline: 1.1911x; 1.1911x over previous
#include <cuda_runtime.h>
#include <cuda_bf16.h>
#include <cstdint>

// ============================================================
// Problem constants
// ============================================================
#define BB    32
#define HID   128
#define ATTN  128
#define S_TOTAL   8192
#define TILE_S    128
#define TILES_PB  (S_TOTAL / TILE_S) // 64
#define CPB       8
#define TILES_PER_CTA (TILES_PB / CPB) // 8
#define NCTA      (BB * CPB)         // 256

// bf16 tile [128 rows][128 cols] with 16B row pad
#define PITCH_H   136
#define PITCH_B   (PITCH_H * 2)      // 272
#define TILE_BYTES (128 * PITCH_B)   // 34816

// SMEM layout (bytes)
#define SMEM_RED    0                      // float[8]
#define SMEM_SCORE  32                     // float[128]
#define SMEM_SW     544                    // float[2][128]
#define SMEM_CORR   1568                   // float[2]
#define SMEM_BIASV  1600                   // float2[128]
#define SMEM_A0     2624
#define SMEM_A1     (SMEM_A0 + TILE_BYTES) // 37440
#define SMEM_W      (SMEM_A1 + TILE_BYTES) // 72256
#define SMEM_TOTAL  (SMEM_W + TILE_BYTES)  // 107072

// Named barriers (0 = __syncthreads)
#define BAR_PROD  1   // 128 producers
#define BAR_CONS  2   // 128 consumers
#define BAR_FULL0 3
#define BAR_FULL1 4
#define BAR_DONE0 5
#define BAR_DONE1 6
#define BAR_SW0   7
#define BAR_SW1   8
#define BAR_ACC0  9
#define BAR_ACC1  10

#define BSYNC(id, n)   asm volatile("bar.sync %0, %1;"   :: "r"(id), "r"(n) : "memory")
#define BARRIVE(id, n) asm volatile("bar.arrive %0, %1;" :: "r"(id), "r"(n) : "memory")
#define MEMBAR_CTA()   asm volatile("membar.cta;" ::: "memory")

// ============================================================
// Partial-result scratch
// ============================================================
__device__ float g_pm[NCTA];
__device__ float g_pl[NCTA];
__device__ float g_pacc[NCTA * HID];

// ============================================================
// Helpers
// ============================================================
__device__ __forceinline__ uint32_t smem_to_u32(const void* p) {
    uint32_t a;
    asm("{ .reg .u64 t; cvta.to.shared.u64 t, %1; cvt.u32.u64 %0, t; }" : "=r"(a) : "l"(p));
    return a;
}

#define LDSM_X4(r, addr) \
    asm volatile("ldmatrix.sync.aligned.m8n8.x4.shared.b16 {%0,%1,%2,%3}, [%4];" \
        : "=r"((r)[0]), "=r"((r)[1]), "=r"((r)[2]), "=r"((r)[3]) : "r"(addr))

__device__ __forceinline__ void mma16816(float* c, const uint32_t* a, uint32_t b0, uint32_t b1) {
    asm volatile(
        "mma.sync.aligned.m16n8k16.row.col.f32.bf16.bf16.f32 "
        "{%0,%1,%2,%3}, {%4,%5,%6,%7}, {%8,%9}, {%0,%1,%2,%3};"
        : "+f"(c[0]), "+f"(c[1]), "+f"(c[2]), "+f"(c[3])
        : "r"(a[0]), "r"(a[1]), "r"(a[2]), "r"(a[3]), "r"(b0), "r"(b1));
}

// [128 x 128] fp32 row-major gmem tile -> bf16 padded smem tile.
// 128 threads: each warp owns one 512B row per iteration (coalesced).
__device__ __forceinline__ void load_tile_bf16(const float4* __restrict__ src4,
                                               char* dst, int wid, int lane) {
#pragma unroll 8
    for (int it = 0; it < 32; ++it) {
        int r = it * 4 + wid;
        float4 v = __ldg(&src4[r * 32 + lane]);
        uint32_t p0, p1;
        asm("cvt.rn.bf16x2.f32 %0, %1, %2;" : "=r"(p0) : "f"(v.y), "f"(v.x));
        asm("cvt.rn.bf16x2.f32 %0, %1, %2;" : "=r"(p1) : "f"(v.w), "f"(v.z));
        *reinterpret_cast<uint2*>(dst + r * PITCH_B + lane * 8) = make_uint2(p0, p1);
    }
}

// ============================================================
// Main fused kernel: warp-specialized producer/consumer pipeline
// ============================================================
__global__ void __launch_bounds__(256, 2) attn_main_kernel(
    const float* __restrict__ hist, const float* __restrict__ cur,
    const float* __restrict__ Wx,   const float* __restrict__ Wxb,
    const float* __restrict__ Wh,   const float* __restrict__ Whb,
    const float* __restrict__ vw)
{
    extern __shared__ __align__(16) char smem[];
    const int tid = threadIdx.x;
    const int cta = blockIdx.x, b = cta >> 3, c = cta & 7;
    const uint32_t sbase = smem_to_u32(smem);

    float* s_red   = reinterpret_cast<float*>(smem + SMEM_RED);
    float* s_score = reinterpret_cast<float*>(smem + SMEM_SCORE);
    float* s_w     = reinterpret_cast<float*>(smem + SMEM_SW);     // [2][128]
    float* s_corr  = reinterpret_cast<float*>(smem + SMEM_CORR);   // [2]
    float2* biasv  = reinterpret_cast<float2*>(smem + SMEM_BIASV);
    char* bufA[2]  = { smem + SMEM_A0, smem + SMEM_A1 };

    const bool is_prod = (tid < 128);

    // ---------- init phase ----------
    if (is_prod) {
        // bias[a] = Whb[a] + Wxb[a] + Wx[a,:].cur[b,:]  (thread a = tid)
        const float* wxa = Wx + tid * HID;
        const float* cb  = cur + b * HID;
        float s = Wxb[tid] + Whb[tid];
#pragma unroll 8
        for (int k = 0; k < HID; ++k) s = fmaf(__ldg(&wxa[k]), __ldg(&cb[k]), s);
        biasv[tid] = make_float2(s, __ldg(&vw[tid]));
    } else {
        // consumers stage Wh tile (rows = attn dim, cols = hid k)
        const int ctid = tid - 128;
        load_tile_bf16(reinterpret_cast<const float4*>(Wh),
                       smem + SMEM_W, ctid >> 5, ctid & 31);
    }
    __syncthreads();

    const float4* histb = reinterpret_cast<const float4*>(
        hist + (size_t)b * S_TOTAL * HID);

    if (is_prod) {
        // ======================= PRODUCER =======================
        const int wid = tid >> 5, lane = tid & 31;
        float facc = 0.f;   // thread owns hid dim = tid

        for (int i = 0; i < TILES_PER_CTA; ++i) {
            const int s = i & 1;
            if (i >= 2) BSYNC(BAR_DONE0 + s, 256);   // consumer done reading buf s (tile i-2)
            const int tile = c + i * CPB;
            load_tile_bf16(histb + (size_t)tile * TILE_S * 32, bufA[s], wid, lane);
            MEMBAR_CTA();
            BARRIVE(BAR_FULL0 + s, 256);

            if (i >= 1) {
                const int p = (i - 1) & 1;
                BSYNC(BAR_SW0 + p, 256);             // weights for tile i-1 published
                const float corr = s_corr[p];
                const float* w = s_w + p * 128;
                const char* hb = bufA[p] + tid * 2;
                facc *= corr;
#pragma unroll 16
                for (int s2 = 0; s2 < TILE_S; ++s2) {
                    uint16_t raw = *reinterpret_cast<const uint16_t*>(hb + s2 * PITCH_B);
                    facc = fmaf(w[s2], __uint_as_float(((uint32_t)raw) << 16), facc);
                }
                BARRIVE(BAR_ACC0 + p, 256);          // s_w slot p reusable
                BSYNC(BAR_PROD, 128);                // all producers done reading buf p
            }
        }
        // epilogue: accumulate last tile
        {
            const int p = (TILES_PER_CTA - 1) & 1;
            BSYNC(BAR_SW0 + p, 256);
            const float corr = s_corr[p];
            const float* w = s_w + p * 128;
            const char* hb = bufA[p] + tid * 2;
            facc *= corr;
#pragma unroll 16
            for (int s2 = 0; s2 < TILE_S; ++s2) {
                uint16_t raw = *reinterpret_cast<const uint16_t*>(hb + s2 * PITCH_B);
                facc = fmaf(w[s2], __uint_as_float(((uint32_t)raw) << 16), facc);
            }
        }
        g_pacc[cta * HID + tid] = facc;
    } else {
        // ======================= CONSUMER =======================
        const int ctid = tid - 128;
        const int cw = ctid >> 5, lane = ctid & 31;
        const uint32_t sW = sbase + SMEM_W;

        const int g8 = lane & 7;
        const uint32_t rowA_off = (uint32_t)((((lane >> 3) & 1) * 8 + g8) * PITCH_B + (lane >> 4) * 16);
        const uint32_t rowB_off = (uint32_t)(((lane >> 4) * 8 + g8) * PITCH_B + ((lane >> 3) & 1) * 16);

        float m_run = __int_as_float(0xff800000);
        float l_run = 0.f;

        for (int i = 0; i < TILES_PER_CTA; ++i) {
            const int s = i & 1;
            BSYNC(BAR_FULL0 + s, 256);
            const uint32_t sA = sbase + (s ? SMEM_A1 : SMEM_A0);

            // ---- GEMM + fused tanh*v reduce ----
            float sp[2][2] = {{0.f, 0.f}, {0.f, 0.f}};
#pragma unroll
            for (int nc = 0; nc < 4; ++nc) {
                float acc[2][4][4];
#pragma unroll
                for (int mt = 0; mt < 2; ++mt)
#pragma unroll
                    for (int nt = 0; nt < 4; ++nt)
#pragma unroll
                        for (int r = 0; r < 4; ++r) acc[mt][nt][r] = 0.f;
#pragma unroll
                for (int k = 0; k < 8; ++k) {
                    uint32_t afr[2][4], bfr[2][4];
#pragma unroll
                    for (int mt = 0; mt < 2; ++mt)
                        LDSM_X4(afr[mt], sA + (uint32_t)((cw * 32 + mt * 16) * PITCH_B + k * 32) + rowA_off);
#pragma unroll
                    for (int ntp = 0; ntp < 2; ++ntp)
                        LDSM_X4(bfr[ntp], sW + (uint32_t)((nc * 32 + ntp * 16) * PITCH_B + k * 32) + rowB_off);
#pragma unroll
                    for (int mt = 0; mt < 2; ++mt)
#pragma unroll
                        for (int nt = 0; nt < 4; ++nt)
                            mma16816(acc[mt][nt], afr[mt],
                                     bfr[nt >> 1][(nt & 1) * 2], bfr[nt >> 1][(nt & 1) * 2 + 1]);
                }
#pragma unroll
                for (int mt = 0; mt < 2; ++mt)
#pragma unroll
                    for (int nt = 0; nt < 4; ++nt) {
                        const int colb = nc * 32 + nt * 8 + 2 * (lane & 3);
                        const float2 bv0 = biasv[colb];
                        const float2 bv1 = biasv[colb + 1];
#pragma unroll
                        for (int rr = 0; rr < 2; ++rr) {
                            float x0 = acc[mt][nt][rr * 2 + 0] + bv0.x;
                            float x1 = acc[mt][nt][rr * 2 + 1] + bv1.x;
                            float t0, t1;
                            asm("tanh.approx.f32 %0, %1;" : "=f"(t0) : "f"(x0));
                            asm("tanh.approx.f32 %0, %1;" : "=f"(t1) : "f"(x1));
                            sp[mt][rr] = fmaf(t0, bv0.y, sp[mt][rr]);
                            sp[mt][rr] = fmaf(t1, bv1.y, sp[mt][rr]);
                        }
                    }
            }
            BARRIVE(BAR_DONE0 + s, 256);  // fragments consumed; buf s free for producer

            // ---- scores -> smem ----
#pragma unroll
            for (int mt = 0; mt < 2; ++mt)
#pragma unroll
                for (int rr = 0; rr < 2; ++rr) {
                    float v = sp[mt][rr];
                    v += __shfl_xor_sync(0xffffffffu, v, 1);
                    v += __shfl_xor_sync(0xffffffffu, v, 2);
                    if ((lane & 3) == 0)
                        s_score[cw * 32 + mt * 16 + rr * 8 + (lane >> 2)] = v;
                }
            BSYNC(BAR_CONS, 128);
            const float score = s_score[ctid];

            // ---- block max over 128 consumers ----
            float mt_ = score;
#pragma unroll
            for (int o = 16; o; o >>= 1) mt_ = fmaxf(mt_, __shfl_xor_sync(0xffffffffu, mt_, o));
            if (lane == 0) s_red[cw] = mt_;
            BSYNC(BAR_CONS, 128);
            const float tmax  = fmaxf(fmaxf(s_red[0], s_red[1]), fmaxf(s_red[2], s_red[3]));
            const float new_m = fmaxf(m_run, tmax);
            const float corr  = __expf(m_run - new_m);
            const float p     = __expf(score - new_m);

            float ps = p;
#pragma unroll
            for (int o = 16; o; o >>= 1) ps += __shfl_xor_sync(0xffffffffu, ps, o);
            if (lane == 0) s_red[4 + cw] = ps;
            BSYNC(BAR_CONS, 128);
            l_run = l_run * corr + (s_red[4] + s_red[5] + s_red[6] + s_red[7]);
            m_run = new_m;

            // ---- publish weights for producers ----
            if (i >= 2) BSYNC(BAR_ACC0 + s, 256);  // accum(i-2) finished with slot s
            s_w[s * 128 + ctid] = p;
            if (ctid == 0) s_corr[s] = corr;
            MEMBAR_CTA();
            BARRIVE(BAR_SW0 + s, 256);
        }
        if (ctid == 0) { g_pm[cta] = m_run; g_pl[cta] = l_run; }
    }
}

// ============================================================
// Combine: merge 8 partials per batch, add cur_h
// ============================================================
__global__ void attn_combine_kernel(const float* __restrict__ cur, float* __restrict__ out)
{
    const int b = blockIdx.x, h = threadIdx.x;
    float M = __int_as_float(0xff800000);
#pragma unroll
    for (int j = 0; j < CPB; ++j) M = fmaxf(M, g_pm[b * CPB + j]);
    float L = 0.f, num = 0.f;
#pragma unroll
    for (int j = 0; j < CPB; ++j) {
        const int idx = b * CPB + j;
        const float e = expf(g_pm[idx] - M);
        L   += g_pl[idx] * e;
        num += g_pacc[idx * HID + h] * e;
    }
    out[b * HID + h] = cur[b * HID + h] + num / L;
}

// ============================================================
// Launch
// ============================================================
extern "C" void kernel_launch(void* const* d_in, const int* in_sizes, int n_in,
                              void* d_out, int out_size)
{
    (void)in_sizes; (void)n_in; (void)out_size;
    const float* cur  = (const float*)d_in[0];
    const float* hist = (const float*)d_in[1];
    const float* Wx   = (const float*)d_in[2];
    const float* Wxb  = (const float*)d_in[3];
    const float* Wh   = (const float*)d_in[4];
    const float* Whb  = (const float*)d_in[5];
    const float* vw   = (const float*)d_in[6];
    float* out = (float*)d_out;

    cudaFuncSetAttribute(attn_main_kernel,
                         cudaFuncAttributeMaxDynamicSharedMemorySize, SMEM_TOTAL);

    attn_main_kernel<<<NCTA, 256, SMEM_TOTAL>>>(hist, cur, Wx, Wxb, Wh, Whb, vw);
    attn_combine_kernel<<<BB, 128>>>(cur, out);
}

// round 5
// speedup vs baseline: 1.3715x; 1.1514x over previous
#include <cuda_runtime.h>
#include <cuda_bf16.h>
#include <cstdint>

// ============================================================
// Problem constants
// ============================================================
#define BB    32
#define HID   128
#define ATTN  128
#define S_TOTAL   8192
#define TILE_S    128
#define TILES_PB  (S_TOTAL / TILE_S) // 64
#define CPB       8
#define TILES_PER_CTA (TILES_PB / CPB) // 8
#define NCTA      (BB * CPB)         // 256

// bf16 tile [128 rows][128 cols] with 16B row pad
#define PITCH_H   136
#define PITCH_B   (PITCH_H * 2)      // 272
#define TILE_BYTES (128 * PITCH_B)   // 34816

// SMEM layout (bytes)
#define SMEM_RED    0                      // float[8] (+ reused as combine flag)
#define SMEM_SCORE  32                     // float[128]
#define SMEM_SW     544                    // float[2][128]
#define SMEM_CORR   1568                   // float[2]
#define SMEM_BIASV  1600                   // float2[128]
#define SMEM_A0     2624
#define SMEM_A1     (SMEM_A0 + TILE_BYTES) // 37440
#define SMEM_W      (SMEM_A1 + TILE_BYTES) // 72256
#define SMEM_TOTAL  (SMEM_W + TILE_BYTES)  // 107072

// Named barriers
#define BAR_PROD  1
#define BAR_CONS  2
#define BAR_FULL0 3
#define BAR_FULL1 4
#define BAR_DONE0 5
#define BAR_DONE1 6
#define BAR_SW0   7
#define BAR_SW1   8
#define BAR_ACC0  9
#define BAR_ACC1  10

#define BSYNC(id, n)   asm volatile("bar.sync %0, %1;"   :: "r"(id), "r"(n) : "memory")
#define BARRIVE(id, n) asm volatile("bar.arrive %0, %1;" :: "r"(id), "r"(n) : "memory")
#define MEMBAR_CTA()   asm volatile("membar.cta;" ::: "memory")

// ============================================================
// Partial-result scratch + combine counters
// ============================================================
__device__ float g_pm[NCTA];
__device__ float g_pl[NCTA];
__device__ float g_pacc[NCTA * HID];
__device__ int   g_cnt[BB];   // zero-init; self-cleaning each launch

// ============================================================
// Helpers
// ============================================================
__device__ __forceinline__ uint32_t smem_to_u32(const void* p) {
    uint32_t a;
    asm("{ .reg .u64 t; cvta.to.shared.u64 t, %1; cvt.u32.u64 %0, t; }" : "=r"(a) : "l"(p));
    return a;
}

#define LDSM_X4(r, addr) \
    asm volatile("ldmatrix.sync.aligned.m8n8.x4.shared.b16 {%0,%1,%2,%3}, [%4];" \
        : "=r"((r)[0]), "=r"((r)[1]), "=r"((r)[2]), "=r"((r)[3]) : "r"(addr))

__device__ __forceinline__ void mma16816(float* c, const uint32_t* a, uint32_t b0, uint32_t b1) {
    asm volatile(
        "mma.sync.aligned.m16n8k16.row.col.f32.bf16.bf16.f32 "
        "{%0,%1,%2,%3}, {%4,%5,%6,%7}, {%8,%9}, {%0,%1,%2,%3};"
        : "+f"(c[0]), "+f"(c[1]), "+f"(c[2]), "+f"(c[3])
        : "r"(a[0]), "r"(a[1]), "r"(a[2]), "r"(a[3]), "r"(b0), "r"(b1));
}

__device__ __forceinline__ float bf_at(const char* p) {
    uint16_t raw = *reinterpret_cast<const uint16_t*>(p);
    return __uint_as_float(((uint32_t)raw) << 16);
}

// [128 x 128] fp32 row-major gmem tile -> bf16 padded smem tile. 128 threads.
__device__ __forceinline__ void load_tile_bf16(const float4* __restrict__ src4,
                                               char* dst, int wid, int lane) {
#pragma unroll 16
    for (int it = 0; it < 32; ++it) {
        int r = it * 4 + wid;
        float4 v = __ldg(&src4[r * 32 + lane]);
        uint32_t p0, p1;
        asm("cvt.rn.bf16x2.f32 %0, %1, %2;" : "=r"(p0) : "f"(v.y), "f"(v.x));
        asm("cvt.rn.bf16x2.f32 %0, %1, %2;" : "=r"(p1) : "f"(v.w), "f"(v.z));
        *reinterpret_cast<uint2*>(dst + r * PITCH_B + lane * 8) = make_uint2(p0, p1);
    }
}

// Weighted accumulate over one tile: 4 independent chains to hide FMA latency.
__device__ __forceinline__ float acc_tile(const char* hb, const float* w, float facc, float corr) {
    float a0 = 0.f, a1 = 0.f, a2 = 0.f, a3 = 0.f;
#pragma unroll
    for (int s2 = 0; s2 < TILE_S; s2 += 4) {
        a0 = fmaf(w[s2 + 0], bf_at(hb + (s2 + 0) * PITCH_B), a0);
        a1 = fmaf(w[s2 + 1], bf_at(hb + (s2 + 1) * PITCH_B), a1);
        a2 = fmaf(w[s2 + 2], bf_at(hb + (s2 + 2) * PITCH_B), a2);
        a3 = fmaf(w[s2 + 3], bf_at(hb + (s2 + 3) * PITCH_B), a3);
    }
    return fmaf(facc, corr, (a0 + a1) + (a2 + a3));
}

// ============================================================
// Main fused kernel (single launch; last CTA per batch combines)
// ============================================================
__global__ void __launch_bounds__(256, 2) attn_main_kernel(
    const float* __restrict__ hist, const float* __restrict__ cur,
    const float* __restrict__ Wx,   const float* __restrict__ Wxb,
    const float* __restrict__ Wh,   const float* __restrict__ Whb,
    const float* __restrict__ vw,   float* __restrict__ out)
{
    extern __shared__ __align__(16) char smem[];
    const int tid = threadIdx.x;
    const int cta = blockIdx.x, b = cta >> 3, c = cta & 7;
    const uint32_t sbase = smem_to_u32(smem);

    float* s_red   = reinterpret_cast<float*>(smem + SMEM_RED);
    float* s_score = reinterpret_cast<float*>(smem + SMEM_SCORE);
    float* s_w     = reinterpret_cast<float*>(smem + SMEM_SW);     // [2][128]
    float* s_corr  = reinterpret_cast<float*>(smem + SMEM_CORR);   // [2]
    float2* biasv  = reinterpret_cast<float2*>(smem + SMEM_BIASV);
    char* bufA[2]  = { smem + SMEM_A0, smem + SMEM_A1 };

    const bool is_prod = (tid < 128);

    // ---------- init phase ----------
    if (is_prod) {
        // Stage Wx transposed into A0/A1 region (coalesced gmem, pad-129 smem),
        // then bias[a] = Whb[a] + Wxb[a] + Wx[a,:].cur[b,:] from smem.
        float* stage = reinterpret_cast<float*>(smem + SMEM_A0);
#pragma unroll 16
        for (int idx = tid; idx < ATTN * HID; idx += 128) {
            int a = idx >> 7, k = idx & 127;
            stage[k * 129 + a] = __ldg(&Wx[idx]);
        }
        BSYNC(BAR_PROD, 128);
        const float* cb = cur + b * HID;
        float s0 = 0.f, s1 = 0.f, s2 = 0.f, s3 = 0.f;
#pragma unroll
        for (int k = 0; k < HID; k += 4) {
            s0 = fmaf(stage[(k + 0) * 129 + tid], __ldg(&cb[k + 0]), s0);
            s1 = fmaf(stage[(k + 1) * 129 + tid], __ldg(&cb[k + 1]), s1);
            s2 = fmaf(stage[(k + 2) * 129 + tid], __ldg(&cb[k + 2]), s2);
            s3 = fmaf(stage[(k + 3) * 129 + tid], __ldg(&cb[k + 3]), s3);
        }
        float s = Wxb[tid] + Whb[tid] + ((s0 + s1) + (s2 + s3));
        biasv[tid] = make_float2(s, __ldg(&vw[tid]));
    } else {
        const int ctid = tid - 128;
        load_tile_bf16(reinterpret_cast<const float4*>(Wh),
                       smem + SMEM_W, ctid >> 5, ctid & 31);
    }
    __syncthreads();

    const float4* histb = reinterpret_cast<const float4*>(
        hist + (size_t)b * S_TOTAL * HID);

    if (is_prod) {
        // ======================= PRODUCER =======================
        const int wid = tid >> 5, lane = tid & 31;
        float facc = 0.f;

        for (int i = 0; i < TILES_PER_CTA; ++i) {
            const int s = i & 1;
            if (i >= 2) BSYNC(BAR_DONE0 + s, 256);
            const int tile = c + i * CPB;
            load_tile_bf16(histb + (size_t)tile * TILE_S * 32, bufA[s], wid, lane);
            MEMBAR_CTA();
            BARRIVE(BAR_FULL0 + s, 256);

            if (i >= 1) {
                const int p = (i - 1) & 1;
                BSYNC(BAR_SW0 + p, 256);
                facc = acc_tile(bufA[p] + tid * 2, s_w + p * 128, facc, s_corr[p]);
                BARRIVE(BAR_ACC0 + p, 256);
                BSYNC(BAR_PROD, 128);
            }
        }
        {
            const int p = (TILES_PER_CTA - 1) & 1;
            BSYNC(BAR_SW0 + p, 256);
            facc = acc_tile(bufA[p] + tid * 2, s_w + p * 128, facc, s_corr[p]);
        }
        g_pacc[cta * HID + tid] = facc;
    } else {
        // ======================= CONSUMER =======================
        const int ctid = tid - 128;
        const int cw = ctid >> 5, lane = ctid & 31;
        const uint32_t sW = sbase + SMEM_W;

        const int g8 = lane & 7;
        const uint32_t rowA_off = (uint32_t)((((lane >> 3) & 1) * 8 + g8) * PITCH_B + (lane >> 4) * 16);
        const uint32_t rowB_off = (uint32_t)(((lane >> 4) * 8 + g8) * PITCH_B + ((lane >> 3) & 1) * 16);

        float m_run = __int_as_float(0xff800000);
        float l_run = 0.f;

        for (int i = 0; i < TILES_PER_CTA; ++i) {
            const int s = i & 1;
            BSYNC(BAR_FULL0 + s, 256);
            const uint32_t sA = sbase + (s ? SMEM_A1 : SMEM_A0);

            float sp[2][2] = {{0.f, 0.f}, {0.f, 0.f}};
#pragma unroll
            for (int nc = 0; nc < 4; ++nc) {
                float acc[2][4][4];
#pragma unroll
                for (int mt = 0; mt < 2; ++mt)
#pragma unroll
                    for (int nt = 0; nt < 4; ++nt)
#pragma unroll
                        for (int r = 0; r < 4; ++r) acc[mt][nt][r] = 0.f;
#pragma unroll
                for (int k = 0; k < 8; ++k) {
                    uint32_t afr[2][4], bfr[2][4];
#pragma unroll
                    for (int mt = 0; mt < 2; ++mt)
                        LDSM_X4(afr[mt], sA + (uint32_t)((cw * 32 + mt * 16) * PITCH_B + k * 32) + rowA_off);
#pragma unroll
                    for (int ntp = 0; ntp < 2; ++ntp)
                        LDSM_X4(bfr[ntp], sW + (uint32_t)((nc * 32 + ntp * 16) * PITCH_B + k * 32) + rowB_off);
#pragma unroll
                    for (int mt = 0; mt < 2; ++mt)
#pragma unroll
                        for (int nt = 0; nt < 4; ++nt)
                            mma16816(acc[mt][nt], afr[mt],
                                     bfr[nt >> 1][(nt & 1) * 2], bfr[nt >> 1][(nt & 1) * 2 + 1]);
                }
#pragma unroll
                for (int mt = 0; mt < 2; ++mt)
#pragma unroll
                    for (int nt = 0; nt < 4; ++nt) {
                        const int colb = nc * 32 + nt * 8 + 2 * (lane & 3);
                        const float2 bv0 = biasv[colb];
                        const float2 bv1 = biasv[colb + 1];
#pragma unroll
                        for (int rr = 0; rr < 2; ++rr) {
                            float x0 = acc[mt][nt][rr * 2 + 0] + bv0.x;
                            float x1 = acc[mt][nt][rr * 2 + 1] + bv1.x;
                            float t0, t1;
                            asm("tanh.approx.f32 %0, %1;" : "=f"(t0) : "f"(x0));
                            asm("tanh.approx.f32 %0, %1;" : "=f"(t1) : "f"(x1));
                            sp[mt][rr] = fmaf(t0, bv0.y, sp[mt][rr]);
                            sp[mt][rr] = fmaf(t1, bv1.y, sp[mt][rr]);
                        }
                    }
            }
            BARRIVE(BAR_DONE0 + s, 256);

#pragma unroll
            for (int mt = 0; mt < 2; ++mt)
#pragma unroll
                for (int rr = 0; rr < 2; ++rr) {
                    float v = sp[mt][rr];
                    v += __shfl_xor_sync(0xffffffffu, v, 1);
                    v += __shfl_xor_sync(0xffffffffu, v, 2);
                    if ((lane & 3) == 0)
                        s_score[cw * 32 + mt * 16 + rr * 8 + (lane >> 2)] = v;
                }
            BSYNC(BAR_CONS, 128);
            const float score = s_score[ctid];

            float mt_ = score;
#pragma unroll
            for (int o = 16; o; o >>= 1) mt_ = fmaxf(mt_, __shfl_xor_sync(0xffffffffu, mt_, o));
            if (lane == 0) s_red[cw] = mt_;
            BSYNC(BAR_CONS, 128);
            const float tmax  = fmaxf(fmaxf(s_red[0], s_red[1]), fmaxf(s_red[2], s_red[3]));
            const float new_m = fmaxf(m_run, tmax);
            const float corr  = __expf(m_run - new_m);
            const float p     = __expf(score - new_m);

            float ps = p;
#pragma unroll
            for (int o = 16; o; o >>= 1) ps += __shfl_xor_sync(0xffffffffu, ps, o);
            if (lane == 0) s_red[4 + cw] = ps;
            BSYNC(BAR_CONS, 128);
            l_run = l_run * corr + (s_red[4] + s_red[5] + s_red[6] + s_red[7]);
            m_run = new_m;

            if (i >= 2) BSYNC(BAR_ACC0 + s, 256);
            s_w[s * 128 + ctid] = p;
            if (ctid == 0) s_corr[s] = corr;
            MEMBAR_CTA();
            BARRIVE(BAR_SW0 + s, 256);
        }
        if (ctid == 0) { g_pm[cta] = m_run; g_pl[cta] = l_run; }
    }

    // ---------- last-CTA-per-batch combine ----------
    __threadfence();
    __syncthreads();
    int* s_flag = reinterpret_cast<int*>(smem + SMEM_RED);
    if (tid == 0) {
        int old = atomicAdd(&g_cnt[b], 1);
        s_flag[0] = (old == CPB - 1) ? 1 : 0;
    }
    __syncthreads();
    if (s_flag[0]) {
        __threadfence();
        if (tid < HID) {
            float M = __int_as_float(0xff800000);
            float pm[CPB], pl[CPB];
#pragma unroll
            for (int j = 0; j < CPB; ++j) {
                pm[j] = __ldcg(&g_pm[b * CPB + j]);
                pl[j] = __ldcg(&g_pl[b * CPB + j]);
                M = fmaxf(M, pm[j]);
            }
            float L = 0.f, num = 0.f;
#pragma unroll
            for (int j = 0; j < CPB; ++j) {
                const float e = __expf(pm[j] - M);
                L   += pl[j] * e;
                num += __ldcg(&g_pacc[(b * CPB + j) * HID + tid]) * e;
            }
            out[b * HID + tid] = cur[b * HID + tid] + num / L;
        }
        if (tid == 0) g_cnt[b] = 0;   // reset for next graph replay
    }
}

// ============================================================
// Launch
// ============================================================
extern "C" void kernel_launch(void* const* d_in, const int* in_sizes, int n_in,
                              void* d_out, int out_size)
{
    (void)in_sizes; (void)n_in; (void)out_size;
    const float* cur  = (const float*)d_in[0];
    const float* hist = (const float*)d_in[1];
    const float* Wx   = (const float*)d_in[2];
    const float* Wxb  = (const float*)d_in[3];
    const float* Wh   = (const float*)d_in[4];
    const float* Whb  = (const float*)d_in[5];
    const float* vw   = (const float*)d_in[6];
    float* out = (float*)d_out;

    cudaFuncSetAttribute(attn_main_kernel,
                         cudaFuncAttributeMaxDynamicSharedMemorySize, SMEM_TOTAL);

    attn_main_kernel<<<NCTA, 256, SMEM_TOTAL>>>(hist, cur, Wx, Wxb, Wh, Whb, vw, out);
}